// round 9
// baseline (speedup 1.0000x reference)
#include <cuda_runtime.h>
#include <cuda_bf16.h>
#include <cstddef>

// Problem constants (fixed shapes per reference)
constexpr int B_ = 16;
constexpr int C_ = 256;
constexpr int L_ = 8192;
constexpr int D_ = 512;   // d_inner
constexpr int A_ = 64;    // att_dim

// Scratch: u[d] = w_out @ wv; coef = <wq,wk>/8; pooled[b,l]
__device__ float g_u[D_];
__device__ float g_coef;
__device__ float g_pooled[B_ * L_];   // 512 KB

// 32 blocks x 256 threads (proven prep). Block g computes u[g*16..g*16+16).
__global__ void prep_kernel(const float* __restrict__ wq,
                            const float* __restrict__ wk,
                            const float* __restrict__ wv,
                            const float* __restrict__ w_out) {
    const int t = threadIdx.x;
    const int g = blockIdx.x;
    const int dl   = t >> 4;
    const int part = t & 15;
    const int d = g * 16 + dl;

    const float4* w4  = reinterpret_cast<const float4*>(w_out + (size_t)d * A_);
    const float4  wv4 = reinterpret_cast<const float4*>(wv)[part];
    const float4  a4  = w4[part];
    float acc = a4.x * wv4.x + a4.y * wv4.y + a4.z * wv4.z + a4.w * wv4.w;
#pragma unroll
    for (int m = 1; m < 16; m <<= 1)
        acc += __shfl_xor_sync(0xffffffffu, acc, m);
    if (part == 0) g_u[d] = acc;

    if (g == 0 && t < 32) {
        float p = wq[t] * wk[t] + wq[t + 32] * wk[t + 32];
#pragma unroll
        for (int m = 16; m >= 1; m >>= 1)
            p += __shfl_xor_sync(0xffffffffu, p, m);
        if (t == 0) g_coef = p * 0.125f;  // 1/sqrt(64)
    }
}

// Kernel A: pooled[b,l] only. One block = (one b, 16 l). 256 threads =
// 16 c-groups x 16 l; h_v read exactly once; writes 64 B per block.
__global__ void __launch_bounds__(256, 6)
pooled_kernel(const float* __restrict__ h_v) {
    __shared__ float s_red[256];
    __shared__ float s_red2[256];
    __shared__ float s_sval[16];

    const int tid = threadIdx.x;
    const int ll  = tid & 15;
    const int cg  = tid >> 4;

    const int bidx   = blockIdx.x;          // 16 * 512 = 8192 blocks
    const int b      = bidx >> 9;
    const int l_base = (bidx & 511) << 4;

    const float coef = g_coef;

    const float* p = h_v + ((size_t)b * C_ + (size_t)cg * 16) * L_ + l_base + ll;
    float h[16];
#pragma unroll
    for (int i = 0; i < 16; i++) h[i] = __ldcs(p + (size_t)i * L_);

    // mean over C
    float sum = 0.f;
#pragma unroll
    for (int i = 0; i < 16; i++) sum += h[i];
    s_red[tid] = sum;
    __syncthreads();
    if (tid < 16) {
        float t = 0.f;
#pragma unroll
        for (int j = 0; j < 16; j++) t += s_red[tid + 16 * j];
        s_sval[tid] = t * ((1.0f / 256.0f) * coef);
    }
    __syncthreads();

    const float coef2 = s_sval[ll];

    // softmax-weighted sum (max-free: |logit| bounded ~1.2)
    float se = 0.f, seh = 0.f;
#pragma unroll
    for (int i = 0; i < 16; i++) {
        float e = __expf(h[i] * coef2);
        se  += e;
        seh += e * h[i];
    }
    s_red[tid]  = se;
    s_red2[tid] = seh;
    __syncthreads();
    if (tid < 16) {
        float te = 0.f, teh = 0.f;
#pragma unroll
        for (int j = 0; j < 16; j++) {
            te  += s_red[tid + 16 * j];
            teh += s_red2[tid + 16 * j];
        }
        g_pooled[(size_t)b * L_ + l_base + tid] = teh / te;
    }
}

// Kernel B: pure outer-product writer. One block = (one b, 64 l).
// 256 threads; each thread stores 32 float4 (full-line warp stores).
// Reads: u (2KB, L2-hot) + 64 pooled floats. Writes 128KB per block.
__global__ void __launch_bounds__(256)
writer_kernel(float* __restrict__ out) {
    __shared__ float s_u[D_];
    __shared__ __align__(16) float s_pooled[64];

    const int tid = threadIdx.x;
    const int bidx   = blockIdx.x;       // 16 * 128 = 2048 blocks
    const int b      = bidx >> 7;
    const int l_base = (bidx & 127) << 6;

    s_u[tid]       = g_u[tid];
    s_u[tid + 256] = g_u[tid + 256];
    if (tid < 64) s_pooled[tid] = g_pooled[(size_t)b * L_ + l_base + tid];
    __syncthreads();

    const int lq = tid & 15;    // 16 float4 = 64 l
    const int d0 = tid >> 4;    // 16 d-groups
    const float4 pv = reinterpret_cast<const float4*>(s_pooled)[lq];
    float4* out4 = reinterpret_cast<float4*>(out + (size_t)b * D_ * L_ + l_base) + lq;
#pragma unroll
    for (int k = 0; k < 32; k++) {
        int d = d0 + 16 * k;
        float ud = s_u[d];
        __stcs(&out4[(size_t)d * (L_ / 4)],
               make_float4(pv.x * ud, pv.y * ud, pv.z * ud, pv.w * ud));
    }
}

extern "C" void kernel_launch(void* const* d_in, const int* in_sizes, int n_in,
                              void* d_out, int out_size) {
    const float* h_v   = (const float*)d_in[0];  // [B, C, L]
    const float* wq    = (const float*)d_in[1];  // [64]
    const float* wk    = (const float*)d_in[2];  // [64]
    const float* wv    = (const float*)d_in[3];  // [64]
    const float* w_out = (const float*)d_in[4];  // [512, 64]
    float* out = (float*)d_out;                  // [B, 512, L]

    prep_kernel<<<D_ / 16, 256>>>(wq, wk, wv, w_out);
    pooled_kernel<<<B_ * (L_ / 16), 256>>>(h_v);
    writer_kernel<<<B_ * (L_ / 64), 256>>>(out);
}